// round 10
// baseline (speedup 1.0000x reference)
#include <cuda_runtime.h>
#include <cuda_bf16.h>
#include <cstdint>

// Problem constants
#define BNUM 8
#define NPTS 8192
#define NPOINTS (BNUM * NPTS)   // 65536
#define TP   32                 // points per block
#define THREADS 512
#define NBLOCKS (NPOINTS / TP)  // 2048
#define OUT_ELEMS ((size_t)NPOINTS * 128)
#define PTS_ELEMS (NPOINTS * 3)

// Per-point row slot (u32 words). fp32 features [16][64]=1024 words during
// gather/Phase-B, then bf16 A: hi pairs at [0,580), lo pairs at [580,1160).
// 1188 % 32 == 4 -> Phase-C A-fragment LDS reads are bank-conflict-free.
#define SLOT 1188
#define HILO 580

// s_wk transposed layout: [p][m][kk] with stride 20 (16 kk + 4 pad, 16B-aligned rows)
#define WKS 20

// Shared memory layout (float words):
//  [0)      s_A[96], s_beff[32], s_l2w[512], s_l2b[16], s_l3w[256], s_l3b[16], s_bias[128] = 1056
//  [1056)   mbarrier (2 words) + pad = 8
//  [1064)   s_wk[32][16][WKS] = 10240
//  [11304)  region: 32 slots x 1188 = 38016
#define OFF_MBAR 1056
#define OFF_WK   1064
#define OFF_REG  11304
#define SMEM_FLOATS (OFF_REG + 32 * SLOT)     // 49320
#define SMEM_BYTES (SMEM_FLOATS * 4)          // 197280 B -> 1 CTA/SM

// Pre-split weight in mma fragment layout: [kt(64)][nt(16)][lane(32)][half(2)] u32
__device__ uint32_t g_whi[65536];
__device__ uint32_t g_wlo[65536];

static __device__ __forceinline__ uint32_t pack2(float x0, float x1) {
    __nv_bfloat162 h = __floats2bfloat162_rn(x0, x1);   // .x = x0 (low half)
    return *reinterpret_cast<uint32_t*>(&h);
}

static __device__ __forceinline__ uint32_t smem_u32(const void* p) {
    uint32_t a;
    asm("{ .reg .u64 t; cvta.to.shared.u64 t, %1; cvt.u32.u64 %0, t; }" : "=r"(a) : "l"(p));
    return a;
}

static __device__ __forceinline__ void mma16816(
    float* d,
    uint32_t a0, uint32_t a1, uint32_t a2, uint32_t a3,
    uint32_t b0, uint32_t b1)
{
    asm volatile(
        "mma.sync.aligned.m16n8k16.row.col.f32.bf16.bf16.f32 "
        "{%0,%1,%2,%3}, {%4,%5,%6,%7}, {%8,%9}, {%0,%1,%2,%3};"
        : "+f"(d[0]), "+f"(d[1]), "+f"(d[2]), "+f"(d[3])
        : "r"(a0), "r"(a1), "r"(a2), "r"(a3), "r"(b0), "r"(b1));
}

// ---------------- fused prep: weight split + output_pts passthrough ----------------
__global__ void prep_and_copy_kernel(const float* __restrict__ w,
                                     const float* __restrict__ pts_src,
                                     float* __restrict__ pts_dst)
{
    const int i = blockIdx.x * blockDim.x + threadIdx.x;

    if (i < 64 * 16 * 32) {                    // weight split (kt, nt, lane)
        const int lane = i & 31;
        const int nt   = (i >> 5) & 15;
        const int kt   = i >> 9;
        const int tk   = lane & 3;
        const int g    = lane >> 2;
        const int n    = nt * 8 + g;
        #pragma unroll
        for (int half = 0; half < 2; half++) {
            const int k0 = kt * 16 + half * 8 + tk * 2;
            const float w0 = w[k0 * 128 + n];
            const float w1 = w[(k0 + 1) * 128 + n];
            const __nv_bfloat16 h0 = __float2bfloat16(w0);
            const __nv_bfloat16 h1 = __float2bfloat16(w1);
            const float l0 = w0 - __bfloat162float(h0);
            const float l1 = w1 - __bfloat162float(h1);
            const int idx = ((kt * 16 + nt) * 32 + lane) * 2 + half;
            g_whi[idx] = pack2(w0, w1);
            g_wlo[idx] = pack2(l0, l1);
        }
    }
    if (i < PTS_ELEMS) pts_dst[i] = pts_src[i];    // output_pts passthrough
}

__global__ void __launch_bounds__(THREADS, 1) ptconv_kernel(
    const float* __restrict__ features,    // [B,N,64]
    const float* __restrict__ input_pts,   // [B,N,3]
    const float* __restrict__ output_pts,  // [B,N,3]
    const int*   __restrict__ indices,     // [B,N,16]
    const float* __restrict__ centers,     // [3,16]
    const float* __restrict__ bias,        // [128]
    const float* __restrict__ l1w,         // [32,48]
    const float* __restrict__ l1b,         // [32]
    const float* __restrict__ l2w,         // [16,32]
    const float* __restrict__ l2b,         // [16]
    const float* __restrict__ l3w,         // [16,16]
    const float* __restrict__ l3b,         // [16]
    float* __restrict__ out)               // [B,N,128]
{
    extern __shared__ float sm[];
    float* s_A    = sm;                 // [3][32]
    float* s_beff = s_A + 96;           // [32]
    float* s_l2w  = s_beff + 32;        // [16][32]
    float* s_l2b  = s_l2w + 512;        // [16]
    float* s_l3w  = s_l2b + 16;         // [16][16]
    float* s_l3b  = s_l3w + 256;        // [16]
    float* s_bias = s_l3b + 16;         // [128]
    float* s_wk   = sm + OFF_WK;        // [32][16][WKS]  (transposed: [p][m][kk])
    uint32_t* s_reg = (uint32_t*)(sm + OFF_REG);   // 32 slots x SLOT

    const int tid = threadIdx.x;
    const uint32_t mbar = smem_u32(sm + OFF_MBAR);
    const uint32_t reg_base = smem_u32(sm + OFF_REG);

    // ---------------- mbarrier init + expect (512 * 256B = 131072B) ----------------
    if (tid == 0) {
        asm volatile("mbarrier.init.shared.b64 [%0], 1;" :: "r"(mbar) : "memory");
        asm volatile("mbarrier.arrive.expect_tx.shared.b64 _, [%0], %1;"
                     :: "r"(mbar), "r"(131072) : "memory");
    }
    __syncthreads();

    // ---------------- Issue feature-row bulk copies; stash relative coords ----------------
    float q0, q1, q2;
    {
        const int p = tid >> 4;          // 0..31
        const int k = tid & 15;
        const int pi = blockIdx.x * TP + p;
        const int b  = pi >> 13;         // N = 8192
        const int idx = indices[pi * 16 + k];
        const int src = (b << 13) + idx;

        q0 = input_pts[src * 3 + 0] - output_pts[pi * 3 + 0];
        q1 = input_pts[src * 3 + 1] - output_pts[pi * 3 + 1];
        q2 = input_pts[src * 3 + 2] - output_pts[pi * 3 + 2];

        const uint32_t dst = reg_base + (uint32_t)(p * SLOT + k * 64) * 4u;
        const float* srcp = features + (size_t)src * 64;
        asm volatile(
            "cp.async.bulk.shared::cta.global.mbarrier::complete_tx::bytes "
            "[%0], [%1], %2, [%3];"
            :: "r"(dst), "l"(srcp), "r"(256), "r"(mbar) : "memory");
    }

    // ---------------- Stage small weights (overlaps with bulk copies) ----------------
    if (tid < 32) {
        const int o = tid;
        float be = l1b[o];
        float a[3];
        #pragma unroll
        for (int j = 0; j < 3; j++) {
            float as = 0.f;
            #pragma unroll
            for (int m = 0; m < 16; m++) {
                float wv = l1w[o * 48 + j * 16 + m];
                be -= centers[j * 16 + m] * wv;
                as += wv;
            }
            a[j] = as;
        }
        s_A[0 * 32 + o] = a[0];
        s_A[1 * 32 + o] = a[1];
        s_A[2 * 32 + o] = a[2];
        s_beff[o] = be;
    }
    if (tid < 512) {
        if (tid < 512 - 0) {}   // (no-op; keep structure)
    }
    for (int i = tid; i < 512; i += THREADS) s_l2w[i] = l2w[i];
    if (tid < 256) s_l3w[tid] = l3w[tid];
    if (tid < 16)  s_l2b[tid] = l2b[tid];
    if (tid < 16)  s_l3b[tid] = l3b[tid];
    if (tid < 128) s_bias[tid] = bias[tid];
    __syncthreads();

    // ---------------- Phase A1: MLP, one (p,k) per thread -> s_wk[p][m][kk] ----------------
    {
        const int p = tid >> 4;
        const int k = tid & 15;
        float h1[32];
        #pragma unroll
        for (int o = 0; o < 32; o++) {
            float v = s_beff[o] + s_A[o] * q0 + s_A[32 + o] * q1 + s_A[64 + o] * q2;
            h1[o] = fmaxf(v, 0.f);
        }
        float h2[16];
        #pragma unroll
        for (int m = 0; m < 16; m++) {
            float acc = s_l2b[m];
            #pragma unroll
            for (int j = 0; j < 32; j++) acc += h1[j] * s_l2w[m * 32 + j];
            h2[m] = fmaxf(acc, 0.f);
        }
        #pragma unroll
        for (int m = 0; m < 16; m++) {
            float acc = s_l3b[m];
            #pragma unroll
            for (int j = 0; j < 16; j++) acc += h2[j] * s_l3w[m * 16 + j];
            s_wk[(p * 16 + m) * WKS + k] = fmaxf(acc, 0.f);   // transposed store
        }
    }

    // ---------------- Wait for feature copies; sync for s_wk visibility ----------------
    {
        uint32_t done;
        asm volatile(
            "{\n\t.reg .pred p;\n\t"
            "mbarrier.try_wait.parity.acquire.cta.shared::cta.b64 p, [%1], 0;\n\t"
            "selp.b32 %0, 1, 0, p;\n\t}"
            : "=r"(done) : "r"(mbar) : "memory");
        while (!done) {
            asm volatile(
                "{\n\t.reg .pred p;\n\t"
                "mbarrier.try_wait.parity.acquire.cta.shared::cta.b64 p, [%1], 0, 0x989680;\n\t"
                "selp.b32 %0, 1, 0, p;\n\t}"
                : "=r"(done) : "r"(mbar) : "memory");
        }
    }
    __syncthreads();

    // ---------------- Phase B: single pass; thread (pb, ci) owns c in {4ci..4ci+3} --------
    {
        const int pb = tid >> 4;        // 0..31
        const int ci = tid & 15;
        float acc[16][4];
        #pragma unroll
        for (int m = 0; m < 16; m++)
            #pragma unroll
            for (int cc = 0; cc < 4; cc++) acc[m][cc] = 0.f;

        #pragma unroll
        for (int kkb = 0; kkb < 4; kkb++) {
            float4 fv[4];
            #pragma unroll
            for (int j = 0; j < 4; j++)
                fv[j] = *reinterpret_cast<const float4*>(
                    &s_reg[pb * SLOT + (kkb * 4 + j) * 64 + ci * 4]);
            #pragma unroll
            for (int m = 0; m < 16; m++) {
                const float4 wk = *reinterpret_cast<const float4*>(
                    &s_wk[(pb * 16 + m) * WKS + kkb * 4]);   // broadcast LDS.128
                acc[m][0] += fv[0].x * wk.x + fv[1].x * wk.y + fv[2].x * wk.z + fv[3].x * wk.w;
                acc[m][1] += fv[0].y * wk.x + fv[1].y * wk.y + fv[2].y * wk.z + fv[3].y * wk.w;
                acc[m][2] += fv[0].z * wk.x + fv[1].z * wk.y + fv[2].z * wk.z + fv[3].z * wk.w;
                acc[m][3] += fv[0].w * wk.x + fv[1].w * wk.y + fv[2].w * wk.z + fv[3].w * wk.w;
            }
        }
        __syncthreads();   // all fp32 reads done -> safe to overwrite slots with bf16
        #pragma unroll
        for (int cc = 0; cc < 4; cc++) {
            const int c = ci * 4 + cc;
            const int base = pb * SLOT + 9 * c;   // hi word; lo at +HILO
            #pragma unroll
            for (int mp = 0; mp < 8; mp++) {
                const float x0 = acc[2 * mp][cc];
                const float x1 = acc[2 * mp + 1][cc];
                const __nv_bfloat162 h = __floats2bfloat162_rn(x0, x1);
                const float l0 = x0 - __bfloat162float(h.x);
                const float l1 = x1 - __bfloat162float(h.y);
                s_reg[base + mp] = *reinterpret_cast<const uint32_t*>(&h);
                s_reg[base + HILO + mp] = pack2(l0, l1);
            }
        }
    }
    __syncthreads();

    // ---------------- Phase C: out[32x128] = A[32x1024] @ W[1024x128], 16 warps ----------
    // warp = (mt = warp>>3, nq = warp&7): 1 m-tile x 2 n-tiles; full k.
    {
        const int lane = tid & 31;
        const int warp = tid >> 5;       // 0..15
        const int tk = lane & 3;
        const int g  = lane >> 2;
        const int mt = warp >> 3;
        const int nq = warp & 7;
        const int nt0 = nq * 2, nt1 = nt0 + 1;

        const uint2* __restrict__ bhi = reinterpret_cast<const uint2*>(g_whi);
        const uint2* __restrict__ blo = reinterpret_cast<const uint2*>(g_wlo);

        float d[2][4];   // [nt][frag]
        #pragma unroll
        for (int nn = 0; nn < 2; nn++)
            #pragma unroll
            for (int qq = 0; qq < 4; qq++) d[nn][qq] = 0.f;

        const int r0 = (mt * 16 + g) * SLOT + tk;
        const int r1 = (mt * 16 + g + 8) * SLOT + tk;
        const int bidx0 = nt0 * 32 + lane;
        const int bidx1 = nt1 * 32 + lane;

        #pragma unroll 4
        for (int kt = 0; kt < 64; kt++) {
            const int ab = kt * 9;
            const uint32_t ah0 = s_reg[r0 + ab];
            const uint32_t ah1 = s_reg[r1 + ab];
            const uint32_t ah2 = s_reg[r0 + ab + 4];
            const uint32_t ah3 = s_reg[r1 + ab + 4];
            const uint32_t al0 = s_reg[r0 + ab + HILO];
            const uint32_t al1 = s_reg[r1 + ab + HILO];
            const uint32_t al2 = s_reg[r0 + ab + HILO + 4];
            const uint32_t al3 = s_reg[r1 + ab + HILO + 4];

            const int bb = kt * 512;
            const uint2 bh0 = bhi[bb + bidx0];
            const uint2 bh1 = bhi[bb + bidx1];
            const uint2 bl0 = blo[bb + bidx0];
            const uint2 bl1 = blo[bb + bidx1];

            mma16816(d[0], ah0, ah1, ah2, ah3, bh0.x, bh0.y);
            mma16816(d[0], ah0, ah1, ah2, ah3, bl0.x, bl0.y);
            mma16816(d[0], al0, al1, al2, al3, bh0.x, bh0.y);
            mma16816(d[1], ah0, ah1, ah2, ah3, bh1.x, bh1.y);
            mma16816(d[1], ah0, ah1, ah2, ah3, bl1.x, bl1.y);
            mma16816(d[1], al0, al1, al2, al3, bh1.x, bh1.y);
        }

        const float inv = 1.f / 16.f;
        const int pibase = blockIdx.x * TP + mt * 16;
        #pragma unroll
        for (int nn = 0; nn < 2; nn++) {
            const int col = (nt0 + nn) * 8 + tk * 2;
            const float b0 = s_bias[col], b1 = s_bias[col + 1];
            *reinterpret_cast<float2*>(&out[(size_t)(pibase + g) * 128 + col]) =
                make_float2(d[nn][0] * inv + b0, d[nn][1] * inv + b1);
            *reinterpret_cast<float2*>(&out[(size_t)(pibase + g + 8) * 128 + col]) =
                make_float2(d[nn][2] * inv + b0, d[nn][3] * inv + b1);
        }
    }
}

extern "C" void kernel_launch(void* const* d_in, const int* in_sizes, int n_in,
                              void* d_out, int out_size)
{
    const float* features   = (const float*)d_in[0];
    const float* input_pts  = (const float*)d_in[1];
    const float* output_pts = (const float*)d_in[2];
    const int*   indices    = (const int*)d_in[3];
    const float* centers    = (const float*)d_in[4];
    const float* weight     = (const float*)d_in[5];
    const float* bias       = (const float*)d_in[6];
    const float* l1w        = (const float*)d_in[7];
    const float* l1b        = (const float*)d_in[8];
    const float* l2w        = (const float*)d_in[9];
    const float* l2b        = (const float*)d_in[10];
    const float* l3w        = (const float*)d_in[11];
    const float* l3b        = (const float*)d_in[12];
    float* out = (float*)d_out;

    cudaFuncSetAttribute(ptconv_kernel, cudaFuncAttributeMaxDynamicSharedMemorySize, SMEM_BYTES);

    // 2 launches per call: fused prep+copy, then main.
    prep_and_copy_kernel<<<(PTS_ELEMS + 255) / 256, 256>>>(weight, output_pts, out + OUT_ELEMS);

    ptconv_kernel<<<NBLOCKS, THREADS, SMEM_BYTES>>>(
        features, input_pts, output_pts, indices, centers, bias,
        l1w, l1b, l2w, l2b, l3w, l3b, out);
}